// round 2
// baseline (speedup 1.0000x reference)
#include <cuda_runtime.h>

// x:   [B=2, 1, D=64, H=256, W=256] fp32
// out: [B=2, 16, D=64, H=256, W=256] fp32
//   even channel -> per-slice 2D sobel magnitude, odd channel -> x
//
// One warp = one image row (256 px). Lane l owns 8 px (2 float4s).
// Vectorized loads (6 LDG.128/thread), halo via warp shuffle, 32 streaming
// STG.128/thread fan-out to the 16 output channels.

#define W 256
#define H 256
#define DD 64
#define NB 2

__global__ __launch_bounds__(256) void sobel_cat_kernel(
    const float* __restrict__ x, float* __restrict__ out)
{
    const int warp = blockIdx.x * (blockDim.x >> 5) + (threadIdx.x >> 5);
    const int lane = threadIdx.x & 31;
    const int h    = warp & (H - 1);
    const int bd   = warp >> 8;         // b*D + d
    const int w0   = lane << 3;         // 8 px per lane

    const float* base = x + ((size_t)bd * H + h) * W + w0;

    float4 z = make_float4(0.f, 0.f, 0.f, 0.f);
    float4 t0 = z, t1 = z, b0 = z, b1 = z;
    float4 m0 = __ldg((const float4*)(base));
    float4 m1 = __ldg((const float4*)(base + 4));
    if (h > 0) {
        t0 = __ldg((const float4*)(base - W));
        t1 = __ldg((const float4*)(base + 4 - W));
    }
    if (h < H - 1) {
        b0 = __ldg((const float4*)(base + W));
        b1 = __ldg((const float4*)(base + 4 + W));
    }

    // halo: w0-1 from lane-1's last elem, w0+8 from lane+1's first elem
    const unsigned full = 0xFFFFFFFFu;
    float tl = __shfl_up_sync(full, t1.w, 1);
    float ml = __shfl_up_sync(full, m1.w, 1);
    float bl = __shfl_up_sync(full, b1.w, 1);
    float tr = __shfl_down_sync(full, t0.x, 1);
    float mr = __shfl_down_sync(full, m0.x, 1);
    float br = __shfl_down_sync(full, b0.x, 1);
    if (lane == 0)  { tl = 0.f; ml = 0.f; bl = 0.f; }
    if (lane == 31) { tr = 0.f; mr = 0.f; br = 0.f; }

    float T[10], M[10], Bt[10];
    T[0] = tl;   M[0] = ml;   Bt[0] = bl;
    T[1] = t0.x; T[2] = t0.y; T[3] = t0.z; T[4] = t0.w;
    T[5] = t1.x; T[6] = t1.y; T[7] = t1.z; T[8] = t1.w; T[9] = tr;
    M[1] = m0.x; M[2] = m0.y; M[3] = m0.z; M[4] = m0.w;
    M[5] = m1.x; M[6] = m1.y; M[7] = m1.z; M[8] = m1.w; M[9] = mr;
    Bt[1] = b0.x; Bt[2] = b0.y; Bt[3] = b0.z; Bt[4] = b0.w;
    Bt[5] = b1.x; Bt[6] = b1.y; Bt[7] = b1.z; Bt[8] = b1.w; Bt[9] = br;

    float sv[8];
#pragma unroll
    for (int i = 0; i < 8; i++) {
        float gx = (T[i + 2] - T[i]) + 2.f * (M[i + 2] - M[i]) + (Bt[i + 2] - Bt[i]);
        float gy = (Bt[i] - T[i]) + 2.f * (Bt[i + 1] - T[i + 1]) + (Bt[i + 2] - T[i + 2]);
        sv[i] = sqrtf(gx * gx + gy * gy);
    }
    float4 s0 = make_float4(sv[0], sv[1], sv[2], sv[3]);
    float4 s1 = make_float4(sv[4], sv[5], sv[6], sv[7]);

    const int b = bd >> 6;            // bd / D
    const int d = bd & (DD - 1);      // bd % D
    const size_t cs = (size_t)DD * H * W;   // channel stride in elems
    float* obase = out + (((size_t)b * 16 * DD + d) * H + h) * W + w0;

#pragma unroll
    for (int c = 0; c < 8; c++) {
        float* p = obase + (size_t)(2 * c) * cs;     // sobel channel
        __stcs((float4*)(p),     s0);
        __stcs((float4*)(p + 4), s1);
        float* q = p + cs;                           // copy channel
        __stcs((float4*)(q),     m0);
        __stcs((float4*)(q + 4), m1);
    }
}

extern "C" void kernel_launch(void* const* d_in, const int* in_sizes, int n_in,
                              void* d_out, int out_size)
{
    const float* x = (const float*)d_in[0];
    float* out = (float*)d_out;

    // one warp per row: NB*DD*H = 32768 warps; 8 warps per block
    const int total_warps = NB * DD * H;
    const int threads = 256;
    const int blocks = total_warps * 32 / threads;   // 4096
    sobel_cat_kernel<<<blocks, threads>>>(x, out);
}

// round 3
// speedup vs baseline: 1.4904x; 1.4904x over previous
#include <cuda_runtime.h>

// x:   [B=2, 1, D=64, H=256, W=256] fp32
// out: [B=2, 16, D=64, H=256, W=256] fp32
//   even channel -> per-slice 2D sobel magnitude, odd channel -> x
//
// Thread = 4 contiguous px (one float4). Warp = 128 contiguous px.
// Loads: 3 x LDG.128 per thread (top/mid/bot rows), halo via warp shuffle,
// cross-warp boundary columns patched by lanes 0/31 with scalar L1-hit loads.
// Stores: 16 x STG.128 streaming fan-out, fully coalesced (512B per warp store).

#define W 256
#define H 256
#define DD 64
#define NB 2

__global__ __launch_bounds__(256) void sobel_cat_kernel(
    const float* __restrict__ x, float* __restrict__ out)
{
    const int t    = blockIdx.x * blockDim.x + threadIdx.x;
    const int lane = threadIdx.x & 31;
    const int wq   = t & 63;          // float4 index within row (W/4 = 64)
    const int row  = t >> 6;          // (b*D + d)*H + h
    const int h    = row & (H - 1);
    const int bd   = row >> 8;
    const int w0   = wq << 2;

    const float* base = x + ((size_t)bd * H + h) * W + w0;
    const bool ht = (h > 0), hb = (h < H - 1);

    float4 z  = make_float4(0.f, 0.f, 0.f, 0.f);
    float4 tv = z, bv = z;
    float4 mv = __ldg((const float4*)base);
    if (ht) tv = __ldg((const float4*)(base - W));
    if (hb) bv = __ldg((const float4*)(base + W));

    // halo from neighbor lanes (warp covers 128 contiguous px of this row)
    const unsigned full = 0xFFFFFFFFu;
    float tl = __shfl_up_sync(full, tv.w, 1);
    float ml = __shfl_up_sync(full, mv.w, 1);
    float bl = __shfl_up_sync(full, bv.w, 1);
    float tr = __shfl_down_sync(full, tv.x, 1);
    float mr = __shfl_down_sync(full, mv.x, 1);
    float br = __shfl_down_sync(full, bv.x, 1);

    // cross-warp / image-edge columns
    if (lane == 0) {
        if (w0 > 0) {
            ml = __ldg(base - 1);
            tl = ht ? __ldg(base - 1 - W) : 0.f;
            bl = hb ? __ldg(base - 1 + W) : 0.f;
        } else { tl = 0.f; ml = 0.f; bl = 0.f; }
    }
    if (lane == 31) {
        if (w0 + 4 < W) {
            mr = __ldg(base + 4);
            tr = ht ? __ldg(base + 4 - W) : 0.f;
            br = hb ? __ldg(base + 4 + W) : 0.f;
        } else { tr = 0.f; mr = 0.f; br = 0.f; }
    }

    float T[6], M[6], Bt[6];
    T[0] = tl;   T[1] = tv.x; T[2] = tv.y; T[3] = tv.z; T[4] = tv.w; T[5] = tr;
    M[0] = ml;   M[1] = mv.x; M[2] = mv.y; M[3] = mv.z; M[4] = mv.w; M[5] = mr;
    Bt[0] = bl;  Bt[1] = bv.x; Bt[2] = bv.y; Bt[3] = bv.z; Bt[4] = bv.w; Bt[5] = br;

    float4 sv;
    float* s = reinterpret_cast<float*>(&sv);
#pragma unroll
    for (int i = 0; i < 4; i++) {
        float gx = (T[i + 2] - T[i]) + 2.f * (M[i + 2] - M[i]) + (Bt[i + 2] - Bt[i]);
        float gy = (Bt[i] - T[i]) + 2.f * (Bt[i + 1] - T[i + 1]) + (Bt[i + 2] - T[i + 2]);
        s[i] = sqrtf(gx * gx + gy * gy);
    }

    const int b = bd >> 6;            // bd / D
    const int d = bd & (DD - 1);      // bd % D
    const size_t cs = (size_t)DD * H * W;   // channel stride (elems)
    float* obase = out + (((size_t)b * 16 * DD + d) * H + h) * W + w0;

#pragma unroll
    for (int c = 0; c < 8; c++) {
        float* p = obase + (size_t)(2 * c) * cs;   // sobel channel
        __stcs((float4*)p, sv);
        __stcs((float4*)(p + cs), mv);             // copy channel
    }
}

extern "C" void kernel_launch(void* const* d_in, const int* in_sizes, int n_in,
                              void* d_out, int out_size)
{
    const float* x = (const float*)d_in[0];
    float* out = (float*)d_out;

    const int total = NB * DD * H * (W / 4);   // 2,097,152 threads
    const int threads = 256;
    const int blocks = total / threads;        // 8192
    sobel_cat_kernel<<<blocks, threads>>>(x, out);
}

// round 4
// speedup vs baseline: 1.5293x; 1.0261x over previous
#include <cuda_runtime.h>

// x:   [B=2, 1, D=64, H=256, W=256] fp32
// out: [B=2, 16, D=64, H=256, W=256] fp32
//   even channel -> per-slice 2D sobel magnitude, odd channel -> x
//
// One warp = one full 256-px row. Lane l owns two float4 chunks: px[4l..4l+3]
// and px[128+4l..128+4l+3]. All halos via warp shuffle (warp owns the whole
// row -> zero scalar edge loads). sqrt.approx (1 MUFU, no refinement).
// 32 fully-coalesced streaming STG.128 per thread.

#define W 256
#define H 256
#define DD 64
#define NB 2

__device__ __forceinline__ float fsqrt_approx(float a) {
    float r;
    asm("sqrt.approx.f32 %0, %1;" : "=f"(r) : "f"(a));
    return r;
}

__global__ __launch_bounds__(256) void sobel_cat_kernel(
    const float* __restrict__ x, float* __restrict__ out)
{
    const int warp = blockIdx.x * (blockDim.x >> 5) + (threadIdx.x >> 5);
    const int lane = threadIdx.x & 31;
    const int h    = warp & (H - 1);
    const int bd   = warp >> 8;          // b*D + d
    const int w0   = lane << 2;          // chunk0: px w0..w0+3, chunk1: +128

    const float* base = x + ((size_t)bd * H + h) * W + w0;
    const bool ht = (h > 0), hb = (h < H - 1);

    float4 z = make_float4(0.f, 0.f, 0.f, 0.f);
    // rows: t=h-1, m=h, b=h+1 ; chunks 0/1
    float4 t0 = z, t1 = z, b0 = z, b1 = z;
    float4 m0 = __ldg((const float4*)base);
    float4 m1 = __ldg((const float4*)(base + 128));
    if (ht) { t0 = __ldg((const float4*)(base - W));
              t1 = __ldg((const float4*)(base + 128 - W)); }
    if (hb) { b0 = __ldg((const float4*)(base + W));
              b1 = __ldg((const float4*)(base + 128 + W)); }

    const unsigned full = 0xFFFFFFFFu;

    // chunk0 halos: left = lane-1 c0.w (lane0 -> 0 pad),
    //               right = lane+1 c0.x (lane31 -> c1.x of lane0)
    float t0l = __shfl_up_sync(full, t0.w, 1);
    float m0l = __shfl_up_sync(full, m0.w, 1);
    float b0l = __shfl_up_sync(full, b0.w, 1);
    float t0r = __shfl_down_sync(full, t0.x, 1);
    float m0r = __shfl_down_sync(full, m0.x, 1);
    float b0r = __shfl_down_sync(full, b0.x, 1);
    float t1x0 = __shfl_sync(full, t1.x, 0);
    float m1x0 = __shfl_sync(full, m1.x, 0);
    float b1x0 = __shfl_sync(full, b1.x, 0);
    if (lane == 0)  { t0l = 0.f; m0l = 0.f; b0l = 0.f; }
    if (lane == 31) { t0r = t1x0; m0r = m1x0; b0r = b1x0; }

    // chunk1 halos: left = lane-1 c1.w (lane0 -> c0.w of lane31),
    //               right = lane+1 c1.x (lane31 -> 0 pad)
    float t1l = __shfl_up_sync(full, t1.w, 1);
    float m1l = __shfl_up_sync(full, m1.w, 1);
    float b1l = __shfl_up_sync(full, b1.w, 1);
    float t1r = __shfl_down_sync(full, t1.x, 1);
    float m1r = __shfl_down_sync(full, m1.x, 1);
    float b1r = __shfl_down_sync(full, b1.x, 1);
    float t0w31 = __shfl_sync(full, t0.w, 31);
    float m0w31 = __shfl_sync(full, m0.w, 31);
    float b0w31 = __shfl_sync(full, b0.w, 31);
    if (lane == 0)  { t1l = t0w31; m1l = m0w31; b1l = b0w31; }
    if (lane == 31) { t1r = 0.f; m1r = 0.f; b1r = 0.f; }

    float4 s0, s1;
    {
        float T[6] = { t0l, t0.x, t0.y, t0.z, t0.w, t0r };
        float M[6] = { m0l, m0.x, m0.y, m0.z, m0.w, m0r };
        float Bt[6] = { b0l, b0.x, b0.y, b0.z, b0.w, b0r };
        float* s = reinterpret_cast<float*>(&s0);
#pragma unroll
        for (int i = 0; i < 4; i++) {
            float gx = (T[i+2] - T[i]) + 2.f*(M[i+2] - M[i]) + (Bt[i+2] - Bt[i]);
            float gy = (Bt[i] - T[i]) + 2.f*(Bt[i+1] - T[i+1]) + (Bt[i+2] - T[i+2]);
            s[i] = fsqrt_approx(gx*gx + gy*gy);
        }
    }
    {
        float T[6] = { t1l, t1.x, t1.y, t1.z, t1.w, t1r };
        float M[6] = { m1l, m1.x, m1.y, m1.z, m1.w, m1r };
        float Bt[6] = { b1l, b1.x, b1.y, b1.z, b1.w, b1r };
        float* s = reinterpret_cast<float*>(&s1);
#pragma unroll
        for (int i = 0; i < 4; i++) {
            float gx = (T[i+2] - T[i]) + 2.f*(M[i+2] - M[i]) + (Bt[i+2] - Bt[i]);
            float gy = (Bt[i] - T[i]) + 2.f*(Bt[i+1] - T[i+1]) + (Bt[i+2] - T[i+2]);
            s[i] = fsqrt_approx(gx*gx + gy*gy);
        }
    }

    const int b = bd >> 6;           // bd / D
    const int d = bd & (DD - 1);     // bd % D
    const size_t cs = (size_t)DD * H * W;  // channel stride (elems)
    float* obase = out + (((size_t)b * 16 * DD + d) * H + h) * W + w0;

#pragma unroll
    for (int c = 0; c < 8; c++) {
        float* p = obase + (size_t)(2 * c) * cs;   // sobel channel
        __stcs((float4*)p,           s0);
        __stcs((float4*)(p + 128),   s1);
        float* q = p + cs;                         // copy channel
        __stcs((float4*)q,           m0);
        __stcs((float4*)(q + 128),   m1);
    }
}

extern "C" void kernel_launch(void* const* d_in, const int* in_sizes, int n_in,
                              void* d_out, int out_size)
{
    const float* x = (const float*)d_in[0];
    float* out = (float*)d_out;

    // one warp per row: NB*DD*H = 32768 warps, 8 warps per block
    const int total_warps = NB * DD * H;
    const int threads = 256;
    const int blocks = total_warps * 32 / threads;   // 4096
    sobel_cat_kernel<<<blocks, threads>>>(x, out);
}